// round 2
// baseline (speedup 1.0000x reference)
#include <cuda_runtime.h>
#include <cstdint>

// Fixed problem shapes
#define T_   8
#define H_   24
#define W_   24
#define HW_  576          // H*W
#define NSP  4608         // T*H*W
#define CIN  256
#define NK   27
#define KD   (CIN * NK)   // 6912

// GEMM tiling
#define BM 128
#define BN 64
#define BK 16
#define TM 8
#define TN 4
#define NTHR 256

// Scratch (static device globals: allocation-free)
__device__ float g_h1[CIN * NSP];
__device__ float g_h2[CIN * NSP];
__device__ float g_off[81 * NSP];

// ---------------------------------------------------------------------------
// conv3d (3x3x3, pad 1) as implicit GEMM:
//   C[M, NSP] = W[M, KD] * B[KD, NSP],  B(k,n) = in[cin, pos+tap] (0-padded)
// ---------------------------------------------------------------------------
template <bool RELU>
__global__ __launch_bounds__(NTHR, 1)
void conv_gemm(float* __restrict__ out, const float* __restrict__ in,
               const float* __restrict__ wgt, const float* __restrict__ bias,
               int M)
{
    __shared__ __align__(16) float As[BK][BM + 4];
    __shared__ __align__(16) float Bs[BK][BN];

    const int tid = threadIdx.x;
    const int bm = blockIdx.y * BM;
    const int bn = blockIdx.x * BN;

    // compute mapping: 16 (n) x 16 (m) threads, each TMxTN
    const int tx = tid & 15;
    const int ty = tid >> 4;
    const int mo = ty * TM;
    const int no = tx * TN;

    // A load mapping: float4 along K
    const int a_kq = tid & 3;    // k quad
    const int a_m  = tid >> 2;   // 0..63, two passes (+64)
    // B load mapping
    const int b_col = tid & 63;
    const int b_kr  = tid >> 6;  // 0..3, 4 passes (+4)

    // spatial decode for this thread's B column (fixed over whole K loop)
    const int n  = bn + b_col;
    const int t  = n / HW_;
    const int hr = n - t * HW_;
    const int h  = hr / W_;
    const int w  = hr - h * W_;

    float acc[TM][TN];
#pragma unroll
    for (int i = 0; i < TM; i++)
#pragma unroll
        for (int j = 0; j < TN; j++) acc[i][j] = 0.f;

    float4 pa[2];
    float  pb[4];

    auto loadA = [&](int k0) {
#pragma unroll
        for (int p = 0; p < 2; p++) {
            int m   = a_m + p * 64;
            int row = bm + m;
            if (row < M) {
                const float* src = wgt + (size_t)row * KD + k0 + a_kq * 4;
                pa[p] = *(const float4*)src;
            } else {
                pa[p] = make_float4(0.f, 0.f, 0.f, 0.f);
            }
        }
    };

    auto loadB = [&](int k0) {
#pragma unroll
        for (int p = 0; p < 4; p++) {
            int kk  = k0 + b_kr + p * 4;
            int cin = kk / NK;
            int tap = kk - cin * NK;
            int dt  = tap / 9;
            int r9  = tap - dt * 9;
            int dh  = r9 / 3;
            int dw  = r9 - dh * 3;
            int zt = t + dt - 1;
            int zh = h + dh - 1;
            int zw = w + dw - 1;
            float v = 0.f;
            if ((unsigned)zt < T_ && (unsigned)zh < H_ && (unsigned)zw < W_)
                v = in[cin * NSP + (zt * H_ + zh) * W_ + zw];
            pb[p] = v;
        }
    };

    auto storeAB = [&]() {
#pragma unroll
        for (int p = 0; p < 2; p++) {
            int m = a_m + p * 64;
            As[a_kq * 4 + 0][m] = pa[p].x;
            As[a_kq * 4 + 1][m] = pa[p].y;
            As[a_kq * 4 + 2][m] = pa[p].z;
            As[a_kq * 4 + 3][m] = pa[p].w;
        }
#pragma unroll
        for (int p = 0; p < 4; p++)
            Bs[b_kr + p * 4][b_col] = pb[p];
    };

    loadA(0);
    loadB(0);
    storeAB();
    __syncthreads();

    const int NT = KD / BK;  // 432
    for (int kt = 0; kt < NT; kt++) {
        const bool more = (kt + 1 < NT);
        if (more) {
            loadA((kt + 1) * BK);
            loadB((kt + 1) * BK);
        }
#pragma unroll
        for (int k = 0; k < BK; k++) {
            float4 a0 = *(const float4*)&As[k][mo];
            float4 a1 = *(const float4*)&As[k][mo + 4];
            float4 b0 = *(const float4*)&Bs[k][no];
            float a[TM] = {a0.x, a0.y, a0.z, a0.w, a1.x, a1.y, a1.z, a1.w};
            float b[TN] = {b0.x, b0.y, b0.z, b0.w};
#pragma unroll
            for (int i = 0; i < TM; i++)
#pragma unroll
                for (int j = 0; j < TN; j++)
                    acc[i][j] = fmaf(a[i], b[j], acc[i][j]);
        }
        __syncthreads();
        if (more) {
            storeAB();
            __syncthreads();
        }
    }

    // epilogue: bias (+ relu), float4 store
#pragma unroll
    for (int i = 0; i < TM; i++) {
        int row = bm + mo + i;
        if (row < M) {
            float bv = bias[row];
            float4 o;
            o.x = acc[i][0] + bv;
            o.y = acc[i][1] + bv;
            o.z = acc[i][2] + bv;
            o.w = acc[i][3] + bv;
            if (RELU) {
                o.x = fmaxf(o.x, 0.f);
                o.y = fmaxf(o.y, 0.f);
                o.z = fmaxf(o.z, 0.f);
                o.w = fmaxf(o.w, 0.f);
            }
            *(float4*)(out + (size_t)row * NSP + bn + no) = o;
        }
    }
}

// ---------------------------------------------------------------------------
// Deformable conv as implicit GEMM with trilinear-gathered B tile.
//   B(cin*27+tap, n) = trilinear(x[cin], base(n) + koff(tap) + off(tap, n))
// Positions (tap, n) cached per block in smem (they don't depend on cin).
// ---------------------------------------------------------------------------
__global__ __launch_bounds__(NTHR, 1)
void deform_gemm(float* __restrict__ out, const float* __restrict__ x,
                 const float* __restrict__ off, const float* __restrict__ wgt,
                 const float* __restrict__ bias)
{
    __shared__ __align__(16) float As[BK][BM + 4];
    __shared__ __align__(16) float Bs[BK][BN];
    __shared__ float ppt[NK * BN];
    __shared__ float pph[NK * BN];
    __shared__ float ppw[NK * BN];

    const int tid = threadIdx.x;
    const int bm = blockIdx.y * BM;
    const int bn = blockIdx.x * BN;

    const int tx = tid & 15;
    const int ty = tid >> 4;
    const int mo = ty * TM;
    const int no = tx * TN;

    const int a_kq = tid & 3;
    const int a_m  = tid >> 2;
    const int b_col = tid & 63;
    const int b_kr  = tid >> 6;

    // Precompute sample positions for all (tap, col) of this block
    for (int e = tid; e < NK * BN; e += NTHR) {
        int tap = e >> 6;           // e / BN
        int col = e & 63;
        int nn = bn + col;
        int tt = nn / HW_;
        int rr = nn - tt * HW_;
        int hh = rr / W_;
        int ww = rr - hh * W_;
        int dt = tap / 9;
        int r9 = tap - dt * 9;
        int dh = r9 / 3;
        int dw = r9 - dh * 3;
        float ot = off[(tap * 3 + 0) * NSP + nn];
        float oh = off[(tap * 3 + 1) * NSP + nn];
        float ow = off[(tap * 3 + 2) * NSP + nn];
        ppt[e] = (float)(tt + dt - 1) + ot;
        pph[e] = (float)(hh + dh - 1) + oh;
        ppw[e] = (float)(ww + dw - 1) + ow;
    }
    __syncthreads();

    float acc[TM][TN];
#pragma unroll
    for (int i = 0; i < TM; i++)
#pragma unroll
        for (int j = 0; j < TN; j++) acc[i][j] = 0.f;

    float4 pa[2];
    float  pb[4];

    auto loadA = [&](int k0) {
#pragma unroll
        for (int p = 0; p < 2; p++) {
            int row = bm + a_m + p * 64;
            const float* src = wgt + (size_t)row * KD + k0 + a_kq * 4;
            pa[p] = *(const float4*)src;
        }
    };

    auto loadB = [&](int k0) {
#pragma unroll
        for (int p = 0; p < 4; p++) {
            int kk  = k0 + b_kr + p * 4;
            int cin = kk / NK;
            int tap = kk - cin * NK;
            int e   = tap * BN + b_col;
            float pt = ppt[e], ph = pph[e], pw = ppw[e];
            float ft = floorf(pt), fh = floorf(ph), fw = floorf(pw);
            float at = pt - ft, ah = ph - fh, aw = pw - fw;
            int it = (int)ft, ih = (int)fh, iw = (int)fw;
            int t1 = it + 1, h1 = ih + 1, w1 = iw + 1;
            float wt0 = ((unsigned)it < T_) ? (1.f - at) : 0.f;
            float wt1 = ((unsigned)t1 < T_) ? at : 0.f;
            float wh0 = ((unsigned)ih < H_) ? (1.f - ah) : 0.f;
            float wh1 = ((unsigned)h1 < H_) ? ah : 0.f;
            float ww0 = ((unsigned)iw < W_) ? (1.f - aw) : 0.f;
            float ww1 = ((unsigned)w1 < W_) ? aw : 0.f;
            int tc0 = min(max(it, 0), T_ - 1), tc1 = min(max(t1, 0), T_ - 1);
            int hc0 = min(max(ih, 0), H_ - 1), hc1 = min(max(h1, 0), H_ - 1);
            int wc0 = min(max(iw, 0), W_ - 1), wc1 = min(max(w1, 0), W_ - 1);
            const float* xc = x + cin * NSP;
            int r00 = (tc0 * H_ + hc0) * W_;
            int r01 = (tc0 * H_ + hc1) * W_;
            int r10 = (tc1 * H_ + hc0) * W_;
            int r11 = (tc1 * H_ + hc1) * W_;
            float w00 = wt0 * wh0, w01 = wt0 * wh1;
            float w10 = wt1 * wh0, w11 = wt1 * wh1;
            float v;
            v  = (w00 * ww0) * xc[r00 + wc0];
            v += (w00 * ww1) * xc[r00 + wc1];
            v += (w01 * ww0) * xc[r01 + wc0];
            v += (w01 * ww1) * xc[r01 + wc1];
            v += (w10 * ww0) * xc[r10 + wc0];
            v += (w10 * ww1) * xc[r10 + wc1];
            v += (w11 * ww0) * xc[r11 + wc0];
            v += (w11 * ww1) * xc[r11 + wc1];
            pb[p] = v;
        }
    };

    auto storeAB = [&]() {
#pragma unroll
        for (int p = 0; p < 2; p++) {
            int m = a_m + p * 64;
            As[a_kq * 4 + 0][m] = pa[p].x;
            As[a_kq * 4 + 1][m] = pa[p].y;
            As[a_kq * 4 + 2][m] = pa[p].z;
            As[a_kq * 4 + 3][m] = pa[p].w;
        }
#pragma unroll
        for (int p = 0; p < 4; p++)
            Bs[b_kr + p * 4][b_col] = pb[p];
    };

    loadA(0);
    loadB(0);
    storeAB();
    __syncthreads();

    const int NT = KD / BK;
    for (int kt = 0; kt < NT; kt++) {
        const bool more = (kt + 1 < NT);
        if (more) {
            loadA((kt + 1) * BK);
            loadB((kt + 1) * BK);
        }
#pragma unroll
        for (int k = 0; k < BK; k++) {
            float4 a0 = *(const float4*)&As[k][mo];
            float4 a1 = *(const float4*)&As[k][mo + 4];
            float4 b0 = *(const float4*)&Bs[k][no];
            float a[TM] = {a0.x, a0.y, a0.z, a0.w, a1.x, a1.y, a1.z, a1.w};
            float b[TN] = {b0.x, b0.y, b0.z, b0.w};
#pragma unroll
            for (int i = 0; i < TM; i++)
#pragma unroll
                for (int j = 0; j < TN; j++)
                    acc[i][j] = fmaf(a[i], b[j], acc[i][j]);
        }
        __syncthreads();
        if (more) {
            storeAB();
            __syncthreads();
        }
    }

#pragma unroll
    for (int i = 0; i < TM; i++) {
        int row = bm + mo + i;
        float bv = bias[row];
        float4 o;
        o.x = acc[i][0] + bv;
        o.y = acc[i][1] + bv;
        o.z = acc[i][2] + bv;
        o.w = acc[i][3] + bv;
        *(float4*)(out + (size_t)row * NSP + bn + no) = o;
    }
}

// ---------------------------------------------------------------------------
extern "C" void kernel_launch(void* const* d_in, const int* in_sizes, int n_in,
                              void* d_out, int out_size)
{
    const float* x    = (const float*)d_in[0];
    const float* l1w  = (const float*)d_in[1];
    const float* l1b  = (const float*)d_in[2];
    const float* l2w  = (const float*)d_in[3];
    const float* l2b  = (const float*)d_in[4];
    const float* l3w  = (const float*)d_in[5];
    const float* l3b  = (const float*)d_in[6];
    const float* dfw  = (const float*)d_in[7];
    const float* dfb  = (const float*)d_in[8];
    const float* c3w  = (const float*)d_in[9];
    const float* c3b  = (const float*)d_in[10];

    float *h1, *h2, *offp;
    cudaGetSymbolAddress((void**)&h1,   g_h1);
    cudaGetSymbolAddress((void**)&h2,   g_h2);
    cudaGetSymbolAddress((void**)&offp, g_off);

    dim3 blk(NTHR);
    dim3 gMain(NSP / BN, (256 + BM - 1) / BM);  // 72 x 2
    dim3 gOff(NSP / BN, 1);                     // 72 x 1 (M=81)

    conv_gemm<true ><<<gMain, blk>>>(h1,   x,  l1w, l1b, 256);
    conv_gemm<true ><<<gMain, blk>>>(h2,   h1, l2w, l2b, 256);
    conv_gemm<true ><<<gMain, blk>>>(h1,   h2, l3w, l3b, 256);
    conv_gemm<false><<<gOff,  blk>>>(offp, h1, dfw, dfb, 81);
    deform_gemm<<<gMain, blk>>>((float*)d_out, x, offp, c3w, c3b);
}

// round 3
// speedup vs baseline: 1.0007x; 1.0007x over previous
#include <cuda_runtime.h>
#include <cstdint>

// Fixed problem shapes
#define T_   8
#define H_   24
#define W_   24
#define HW_  576          // H*W
#define NSP  4608         // T*H*W
#define CIN  256
#define NK   27
#define KD   (CIN * NK)   // 6912

// GEMM tiling
#define BM 128
#define BN 64
#define BK 16
#define TM 8
#define TN 4
#define NTHR 256

// Scratch (static device globals: allocation-free)
__device__ float g_h1[CIN * NSP];
__device__ float g_h2[CIN * NSP];
__device__ float g_off[81 * NSP];

// ---------------------------------------------------------------------------
// conv3d (3x3x3, pad 1) as implicit GEMM:
//   C[M, NSP] = W[M, KD] * B[KD, NSP],  B(k,n) = in[cin, pos+tap] (0-padded)
// ---------------------------------------------------------------------------
template <bool RELU>
__global__ __launch_bounds__(NTHR, 1)
void conv_gemm(float* __restrict__ out, const float* __restrict__ in,
               const float* __restrict__ wgt, const float* __restrict__ bias,
               int M)
{
    __shared__ __align__(16) float As[BK][BM + 4];
    __shared__ __align__(16) float Bs[BK][BN];

    const int tid = threadIdx.x;
    const int bm = blockIdx.y * BM;
    const int bn = blockIdx.x * BN;

    // compute mapping: 16 (n) x 16 (m) threads, each TMxTN
    const int tx = tid & 15;
    const int ty = tid >> 4;
    const int mo = ty * TM;
    const int no = tx * TN;

    // A load mapping: float4 along K
    const int a_kq = tid & 3;    // k quad
    const int a_m  = tid >> 2;   // 0..63, two passes (+64)
    // B load mapping
    const int b_col = tid & 63;
    const int b_kr  = tid >> 6;  // 0..3, 4 passes (+4)

    // spatial decode for this thread's B column (fixed over whole K loop)
    const int n  = bn + b_col;
    const int t  = n / HW_;
    const int hr = n - t * HW_;
    const int h  = hr / W_;
    const int w  = hr - h * W_;

    float acc[TM][TN];
#pragma unroll
    for (int i = 0; i < TM; i++)
#pragma unroll
        for (int j = 0; j < TN; j++) acc[i][j] = 0.f;

    float4 pa[2];
    float  pb[4];

    auto loadA = [&](int k0) {
#pragma unroll
        for (int p = 0; p < 2; p++) {
            int m   = a_m + p * 64;
            int row = bm + m;
            if (row < M) {
                const float* src = wgt + (size_t)row * KD + k0 + a_kq * 4;
                pa[p] = *(const float4*)src;
            } else {
                pa[p] = make_float4(0.f, 0.f, 0.f, 0.f);
            }
        }
    };

    auto loadB = [&](int k0) {
#pragma unroll
        for (int p = 0; p < 4; p++) {
            int kk  = k0 + b_kr + p * 4;
            int cin = kk / NK;
            int tap = kk - cin * NK;
            int dt  = tap / 9;
            int r9  = tap - dt * 9;
            int dh  = r9 / 3;
            int dw  = r9 - dh * 3;
            int zt = t + dt - 1;
            int zh = h + dh - 1;
            int zw = w + dw - 1;
            float v = 0.f;
            if ((unsigned)zt < T_ && (unsigned)zh < H_ && (unsigned)zw < W_)
                v = in[cin * NSP + (zt * H_ + zh) * W_ + zw];
            pb[p] = v;
        }
    };

    auto storeAB = [&]() {
#pragma unroll
        for (int p = 0; p < 2; p++) {
            int m = a_m + p * 64;
            As[a_kq * 4 + 0][m] = pa[p].x;
            As[a_kq * 4 + 1][m] = pa[p].y;
            As[a_kq * 4 + 2][m] = pa[p].z;
            As[a_kq * 4 + 3][m] = pa[p].w;
        }
#pragma unroll
        for (int p = 0; p < 4; p++)
            Bs[b_kr + p * 4][b_col] = pb[p];
    };

    loadA(0);
    loadB(0);
    storeAB();
    __syncthreads();

    const int NT = KD / BK;  // 432
    for (int kt = 0; kt < NT; kt++) {
        const bool more = (kt + 1 < NT);
        if (more) {
            loadA((kt + 1) * BK);
            loadB((kt + 1) * BK);
        }
#pragma unroll
        for (int k = 0; k < BK; k++) {
            float4 a0 = *(const float4*)&As[k][mo];
            float4 a1 = *(const float4*)&As[k][mo + 4];
            float4 b0 = *(const float4*)&Bs[k][no];
            float a[TM] = {a0.x, a0.y, a0.z, a0.w, a1.x, a1.y, a1.z, a1.w};
            float b[TN] = {b0.x, b0.y, b0.z, b0.w};
#pragma unroll
            for (int i = 0; i < TM; i++)
#pragma unroll
                for (int j = 0; j < TN; j++)
                    acc[i][j] = fmaf(a[i], b[j], acc[i][j]);
        }
        __syncthreads();
        if (more) {
            storeAB();
            __syncthreads();
        }
    }

    // epilogue: bias (+ relu), float4 store
#pragma unroll
    for (int i = 0; i < TM; i++) {
        int row = bm + mo + i;
        if (row < M) {
            float bv = bias[row];
            float4 o;
            o.x = acc[i][0] + bv;
            o.y = acc[i][1] + bv;
            o.z = acc[i][2] + bv;
            o.w = acc[i][3] + bv;
            if (RELU) {
                o.x = fmaxf(o.x, 0.f);
                o.y = fmaxf(o.y, 0.f);
                o.z = fmaxf(o.z, 0.f);
                o.w = fmaxf(o.w, 0.f);
            }
            *(float4*)(out + (size_t)row * NSP + bn + no) = o;
        }
    }
}

// ---------------------------------------------------------------------------
// Deformable conv as implicit GEMM with trilinear-gathered B tile.
//   B(cin*27+tap, n) = trilinear(x[cin], base(n) + koff(tap) + off(tap, n))
// Positions (tap, n) cached per block in smem (they don't depend on cin).
// ---------------------------------------------------------------------------
__global__ __launch_bounds__(NTHR, 1)
void deform_gemm(float* __restrict__ out, const float* __restrict__ x,
                 const float* __restrict__ off, const float* __restrict__ wgt,
                 const float* __restrict__ bias)
{
    __shared__ __align__(16) float As[BK][BM + 4];
    __shared__ __align__(16) float Bs[BK][BN];
    __shared__ float ppt[NK * BN];
    __shared__ float pph[NK * BN];
    __shared__ float ppw[NK * BN];

    const int tid = threadIdx.x;
    const int bm = blockIdx.y * BM;
    const int bn = blockIdx.x * BN;

    const int tx = tid & 15;
    const int ty = tid >> 4;
    const int mo = ty * TM;
    const int no = tx * TN;

    const int a_kq = tid & 3;
    const int a_m  = tid >> 2;
    const int b_col = tid & 63;
    const int b_kr  = tid >> 6;

    // Precompute sample positions for all (tap, col) of this block
    for (int e = tid; e < NK * BN; e += NTHR) {
        int tap = e >> 6;           // e / BN
        int col = e & 63;
        int nn = bn + col;
        int tt = nn / HW_;
        int rr = nn - tt * HW_;
        int hh = rr / W_;
        int ww = rr - hh * W_;
        int dt = tap / 9;
        int r9 = tap - dt * 9;
        int dh = r9 / 3;
        int dw = r9 - dh * 3;
        float ot = off[(tap * 3 + 0) * NSP + nn];
        float oh = off[(tap * 3 + 1) * NSP + nn];
        float ow = off[(tap * 3 + 2) * NSP + nn];
        ppt[e] = (float)(tt + dt - 1) + ot;
        pph[e] = (float)(hh + dh - 1) + oh;
        ppw[e] = (float)(ww + dw - 1) + ow;
    }
    __syncthreads();

    float acc[TM][TN];
#pragma unroll
    for (int i = 0; i < TM; i++)
#pragma unroll
        for (int j = 0; j < TN; j++) acc[i][j] = 0.f;

    float4 pa[2];
    float  pb[4];

    auto loadA = [&](int k0) {
#pragma unroll
        for (int p = 0; p < 2; p++) {
            int row = bm + a_m + p * 64;
            const float* src = wgt + (size_t)row * KD + k0 + a_kq * 4;
            pa[p] = *(const float4*)src;
        }
    };

    auto loadB = [&](int k0) {
#pragma unroll
        for (int p = 0; p < 4; p++) {
            int kk  = k0 + b_kr + p * 4;
            int cin = kk / NK;
            int tap = kk - cin * NK;
            int e   = tap * BN + b_col;
            float pt = ppt[e], ph = pph[e], pw = ppw[e];
            float ft = floorf(pt), fh = floorf(ph), fw = floorf(pw);
            float at = pt - ft, ah = ph - fh, aw = pw - fw;
            int it = (int)ft, ih = (int)fh, iw = (int)fw;
            int t1 = it + 1, h1 = ih + 1, w1 = iw + 1;
            float wt0 = ((unsigned)it < T_) ? (1.f - at) : 0.f;
            float wt1 = ((unsigned)t1 < T_) ? at : 0.f;
            float wh0 = ((unsigned)ih < H_) ? (1.f - ah) : 0.f;
            float wh1 = ((unsigned)h1 < H_) ? ah : 0.f;
            float ww0 = ((unsigned)iw < W_) ? (1.f - aw) : 0.f;
            float ww1 = ((unsigned)w1 < W_) ? aw : 0.f;
            int tc0 = min(max(it, 0), T_ - 1), tc1 = min(max(t1, 0), T_ - 1);
            int hc0 = min(max(ih, 0), H_ - 1), hc1 = min(max(h1, 0), H_ - 1);
            int wc0 = min(max(iw, 0), W_ - 1), wc1 = min(max(w1, 0), W_ - 1);
            const float* xc = x + cin * NSP;
            int r00 = (tc0 * H_ + hc0) * W_;
            int r01 = (tc0 * H_ + hc1) * W_;
            int r10 = (tc1 * H_ + hc0) * W_;
            int r11 = (tc1 * H_ + hc1) * W_;
            float w00 = wt0 * wh0, w01 = wt0 * wh1;
            float w10 = wt1 * wh0, w11 = wt1 * wh1;
            float v;
            v  = (w00 * ww0) * xc[r00 + wc0];
            v += (w00 * ww1) * xc[r00 + wc1];
            v += (w01 * ww0) * xc[r01 + wc0];
            v += (w01 * ww1) * xc[r01 + wc1];
            v += (w10 * ww0) * xc[r10 + wc0];
            v += (w10 * ww1) * xc[r10 + wc1];
            v += (w11 * ww0) * xc[r11 + wc0];
            v += (w11 * ww1) * xc[r11 + wc1];
            pb[p] = v;
        }
    };

    auto storeAB = [&]() {
#pragma unroll
        for (int p = 0; p < 2; p++) {
            int m = a_m + p * 64;
            As[a_kq * 4 + 0][m] = pa[p].x;
            As[a_kq * 4 + 1][m] = pa[p].y;
            As[a_kq * 4 + 2][m] = pa[p].z;
            As[a_kq * 4 + 3][m] = pa[p].w;
        }
#pragma unroll
        for (int p = 0; p < 4; p++)
            Bs[b_kr + p * 4][b_col] = pb[p];
    };

    loadA(0);
    loadB(0);
    storeAB();
    __syncthreads();

    const int NT = KD / BK;
    for (int kt = 0; kt < NT; kt++) {
        const bool more = (kt + 1 < NT);
        if (more) {
            loadA((kt + 1) * BK);
            loadB((kt + 1) * BK);
        }
#pragma unroll
        for (int k = 0; k < BK; k++) {
            float4 a0 = *(const float4*)&As[k][mo];
            float4 a1 = *(const float4*)&As[k][mo + 4];
            float4 b0 = *(const float4*)&Bs[k][no];
            float a[TM] = {a0.x, a0.y, a0.z, a0.w, a1.x, a1.y, a1.z, a1.w};
            float b[TN] = {b0.x, b0.y, b0.z, b0.w};
#pragma unroll
            for (int i = 0; i < TM; i++)
#pragma unroll
                for (int j = 0; j < TN; j++)
                    acc[i][j] = fmaf(a[i], b[j], acc[i][j]);
        }
        __syncthreads();
        if (more) {
            storeAB();
            __syncthreads();
        }
    }

#pragma unroll
    for (int i = 0; i < TM; i++) {
        int row = bm + mo + i;
        float bv = bias[row];
        float4 o;
        o.x = acc[i][0] + bv;
        o.y = acc[i][1] + bv;
        o.z = acc[i][2] + bv;
        o.w = acc[i][3] + bv;
        *(float4*)(out + (size_t)row * NSP + bn + no) = o;
    }
}

// ---------------------------------------------------------------------------
extern "C" void kernel_launch(void* const* d_in, const int* in_sizes, int n_in,
                              void* d_out, int out_size)
{
    const float* x    = (const float*)d_in[0];
    const float* l1w  = (const float*)d_in[1];
    const float* l1b  = (const float*)d_in[2];
    const float* l2w  = (const float*)d_in[3];
    const float* l2b  = (const float*)d_in[4];
    const float* l3w  = (const float*)d_in[5];
    const float* l3b  = (const float*)d_in[6];
    const float* dfw  = (const float*)d_in[7];
    const float* dfb  = (const float*)d_in[8];
    const float* c3w  = (const float*)d_in[9];
    const float* c3b  = (const float*)d_in[10];

    float *h1, *h2, *offp;
    cudaGetSymbolAddress((void**)&h1,   g_h1);
    cudaGetSymbolAddress((void**)&h2,   g_h2);
    cudaGetSymbolAddress((void**)&offp, g_off);

    dim3 blk(NTHR);
    dim3 gMain(NSP / BN, (256 + BM - 1) / BM);  // 72 x 2
    dim3 gOff(NSP / BN, 1);                     // 72 x 1 (M=81)

    conv_gemm<true ><<<gMain, blk>>>(h1,   x,  l1w, l1b, 256);
    conv_gemm<true ><<<gMain, blk>>>(h2,   h1, l2w, l2b, 256);
    conv_gemm<true ><<<gMain, blk>>>(h1,   h2, l3w, l3b, 256);
    conv_gemm<false><<<gOff,  blk>>>(offp, h1, dfw, dfb, 81);
    deform_gemm<<<gMain, blk>>>((float*)d_out, x, offp, c3w, c3b);
}

// round 4
// speedup vs baseline: 1.0025x; 1.0018x over previous
#include <cuda_runtime.h>
#include <cstdint>

// Fixed problem shapes
#define T_   8
#define H_   24
#define W_   24
#define HW_  576          // H*W
#define NSP  4608         // T*H*W
#define CIN  256
#define NK   27
#define KD   (CIN * NK)   // 6912

// GEMM tiling
#define BM 128
#define BN 64
#define BK 16
#define TM 8
#define TN 4
#define NTHR 256

// Scratch (static device globals: allocation-free)
__device__ float g_h1[CIN * NSP];
__device__ float g_h2[CIN * NSP];
__device__ float g_off[81 * NSP];

// ---------------------------------------------------------------------------
// conv3d (3x3x3, pad 1) as implicit GEMM:
//   C[M, NSP] = W[M, KD] * B[KD, NSP],  B(k,n) = in[cin, pos+tap] (0-padded)
// ---------------------------------------------------------------------------
template <bool RELU>
__global__ __launch_bounds__(NTHR, 1)
void conv_gemm(float* __restrict__ out, const float* __restrict__ in,
               const float* __restrict__ wgt, const float* __restrict__ bias,
               int M)
{
    __shared__ __align__(16) float As[BK][BM + 4];
    __shared__ __align__(16) float Bs[BK][BN];

    const int tid = threadIdx.x;
    const int bm = blockIdx.y * BM;
    const int bn = blockIdx.x * BN;

    // compute mapping: 16 (n) x 16 (m) threads, each TMxTN
    const int tx = tid & 15;
    const int ty = tid >> 4;
    const int mo = ty * TM;
    const int no = tx * TN;

    // A load mapping: float4 along K
    const int a_kq = tid & 3;    // k quad
    const int a_m  = tid >> 2;   // 0..63, two passes (+64)
    // B load mapping
    const int b_col = tid & 63;
    const int b_kr  = tid >> 6;  // 0..3, 4 passes (+4)

    // spatial decode for this thread's B column (fixed over whole K loop)
    const int n  = bn + b_col;
    const int t  = n / HW_;
    const int hr = n - t * HW_;
    const int h  = hr / W_;
    const int w  = hr - h * W_;

    float acc[TM][TN];
#pragma unroll
    for (int i = 0; i < TM; i++)
#pragma unroll
        for (int j = 0; j < TN; j++) acc[i][j] = 0.f;

    float4 pa[2];
    float  pb[4];

    auto loadA = [&](int k0) {
#pragma unroll
        for (int p = 0; p < 2; p++) {
            int m   = a_m + p * 64;
            int row = bm + m;
            if (row < M) {
                const float* src = wgt + (size_t)row * KD + k0 + a_kq * 4;
                pa[p] = *(const float4*)src;
            } else {
                pa[p] = make_float4(0.f, 0.f, 0.f, 0.f);
            }
        }
    };

    auto loadB = [&](int k0) {
#pragma unroll
        for (int p = 0; p < 4; p++) {
            int kk  = k0 + b_kr + p * 4;
            int cin = kk / NK;
            int tap = kk - cin * NK;
            int dt  = tap / 9;
            int r9  = tap - dt * 9;
            int dh  = r9 / 3;
            int dw  = r9 - dh * 3;
            int zt = t + dt - 1;
            int zh = h + dh - 1;
            int zw = w + dw - 1;
            float v = 0.f;
            if ((unsigned)zt < T_ && (unsigned)zh < H_ && (unsigned)zw < W_)
                v = in[cin * NSP + (zt * H_ + zh) * W_ + zw];
            pb[p] = v;
        }
    };

    auto storeAB = [&]() {
#pragma unroll
        for (int p = 0; p < 2; p++) {
            int m = a_m + p * 64;
            As[a_kq * 4 + 0][m] = pa[p].x;
            As[a_kq * 4 + 1][m] = pa[p].y;
            As[a_kq * 4 + 2][m] = pa[p].z;
            As[a_kq * 4 + 3][m] = pa[p].w;
        }
#pragma unroll
        for (int p = 0; p < 4; p++)
            Bs[b_kr + p * 4][b_col] = pb[p];
    };

    loadA(0);
    loadB(0);
    storeAB();
    __syncthreads();

    const int NT = KD / BK;  // 432
    for (int kt = 0; kt < NT; kt++) {
        const bool more = (kt + 1 < NT);
        if (more) {
            loadA((kt + 1) * BK);
            loadB((kt + 1) * BK);
        }
#pragma unroll
        for (int k = 0; k < BK; k++) {
            float4 a0 = *(const float4*)&As[k][mo];
            float4 a1 = *(const float4*)&As[k][mo + 4];
            float4 b0 = *(const float4*)&Bs[k][no];
            float a[TM] = {a0.x, a0.y, a0.z, a0.w, a1.x, a1.y, a1.z, a1.w};
            float b[TN] = {b0.x, b0.y, b0.z, b0.w};
#pragma unroll
            for (int i = 0; i < TM; i++)
#pragma unroll
                for (int j = 0; j < TN; j++)
                    acc[i][j] = fmaf(a[i], b[j], acc[i][j]);
        }
        __syncthreads();
        if (more) {
            storeAB();
            __syncthreads();
        }
    }

    // epilogue: bias (+ relu), float4 store
#pragma unroll
    for (int i = 0; i < TM; i++) {
        int row = bm + mo + i;
        if (row < M) {
            float bv = bias[row];
            float4 o;
            o.x = acc[i][0] + bv;
            o.y = acc[i][1] + bv;
            o.z = acc[i][2] + bv;
            o.w = acc[i][3] + bv;
            if (RELU) {
                o.x = fmaxf(o.x, 0.f);
                o.y = fmaxf(o.y, 0.f);
                o.z = fmaxf(o.z, 0.f);
                o.w = fmaxf(o.w, 0.f);
            }
            *(float4*)(out + (size_t)row * NSP + bn + no) = o;
        }
    }
}

// ---------------------------------------------------------------------------
// Deformable conv as implicit GEMM with trilinear-gathered B tile.
//   B(cin*27+tap, n) = trilinear(x[cin], base(n) + koff(tap) + off(tap, n))
// Positions (tap, n) cached per block in smem (they don't depend on cin).
// ---------------------------------------------------------------------------
__global__ __launch_bounds__(NTHR, 1)
void deform_gemm(float* __restrict__ out, const float* __restrict__ x,
                 const float* __restrict__ off, const float* __restrict__ wgt,
                 const float* __restrict__ bias)
{
    __shared__ __align__(16) float As[BK][BM + 4];
    __shared__ __align__(16) float Bs[BK][BN];
    __shared__ float ppt[NK * BN];
    __shared__ float pph[NK * BN];
    __shared__ float ppw[NK * BN];

    const int tid = threadIdx.x;
    const int bm = blockIdx.y * BM;
    const int bn = blockIdx.x * BN;

    const int tx = tid & 15;
    const int ty = tid >> 4;
    const int mo = ty * TM;
    const int no = tx * TN;

    const int a_kq = tid & 3;
    const int a_m  = tid >> 2;
    const int b_col = tid & 63;
    const int b_kr  = tid >> 6;

    // Precompute sample positions for all (tap, col) of this block
    for (int e = tid; e < NK * BN; e += NTHR) {
        int tap = e >> 6;           // e / BN
        int col = e & 63;
        int nn = bn + col;
        int tt = nn / HW_;
        int rr = nn - tt * HW_;
        int hh = rr / W_;
        int ww = rr - hh * W_;
        int dt = tap / 9;
        int r9 = tap - dt * 9;
        int dh = r9 / 3;
        int dw = r9 - dh * 3;
        float ot = off[(tap * 3 + 0) * NSP + nn];
        float oh = off[(tap * 3 + 1) * NSP + nn];
        float ow = off[(tap * 3 + 2) * NSP + nn];
        ppt[e] = (float)(tt + dt - 1) + ot;
        pph[e] = (float)(hh + dh - 1) + oh;
        ppw[e] = (float)(ww + dw - 1) + ow;
    }
    __syncthreads();

    float acc[TM][TN];
#pragma unroll
    for (int i = 0; i < TM; i++)
#pragma unroll
        for (int j = 0; j < TN; j++) acc[i][j] = 0.f;

    float4 pa[2];
    float  pb[4];

    auto loadA = [&](int k0) {
#pragma unroll
        for (int p = 0; p < 2; p++) {
            int row = bm + a_m + p * 64;
            const float* src = wgt + (size_t)row * KD + k0 + a_kq * 4;
            pa[p] = *(const float4*)src;
        }
    };

    auto loadB = [&](int k0) {
#pragma unroll
        for (int p = 0; p < 4; p++) {
            int kk  = k0 + b_kr + p * 4;
            int cin = kk / NK;
            int tap = kk - cin * NK;
            int e   = tap * BN + b_col;
            float pt = ppt[e], ph = pph[e], pw = ppw[e];
            float ft = floorf(pt), fh = floorf(ph), fw = floorf(pw);
            float at = pt - ft, ah = ph - fh, aw = pw - fw;
            int it = (int)ft, ih = (int)fh, iw = (int)fw;
            int t1 = it + 1, h1 = ih + 1, w1 = iw + 1;
            float wt0 = ((unsigned)it < T_) ? (1.f - at) : 0.f;
            float wt1 = ((unsigned)t1 < T_) ? at : 0.f;
            float wh0 = ((unsigned)ih < H_) ? (1.f - ah) : 0.f;
            float wh1 = ((unsigned)h1 < H_) ? ah : 0.f;
            float ww0 = ((unsigned)iw < W_) ? (1.f - aw) : 0.f;
            float ww1 = ((unsigned)w1 < W_) ? aw : 0.f;
            int tc0 = min(max(it, 0), T_ - 1), tc1 = min(max(t1, 0), T_ - 1);
            int hc0 = min(max(ih, 0), H_ - 1), hc1 = min(max(h1, 0), H_ - 1);
            int wc0 = min(max(iw, 0), W_ - 1), wc1 = min(max(w1, 0), W_ - 1);
            const float* xc = x + cin * NSP;
            int r00 = (tc0 * H_ + hc0) * W_;
            int r01 = (tc0 * H_ + hc1) * W_;
            int r10 = (tc1 * H_ + hc0) * W_;
            int r11 = (tc1 * H_ + hc1) * W_;
            float w00 = wt0 * wh0, w01 = wt0 * wh1;
            float w10 = wt1 * wh0, w11 = wt1 * wh1;
            float v;
            v  = (w00 * ww0) * xc[r00 + wc0];
            v += (w00 * ww1) * xc[r00 + wc1];
            v += (w01 * ww0) * xc[r01 + wc0];
            v += (w01 * ww1) * xc[r01 + wc1];
            v += (w10 * ww0) * xc[r10 + wc0];
            v += (w10 * ww1) * xc[r10 + wc1];
            v += (w11 * ww0) * xc[r11 + wc0];
            v += (w11 * ww1) * xc[r11 + wc1];
            pb[p] = v;
        }
    };

    auto storeAB = [&]() {
#pragma unroll
        for (int p = 0; p < 2; p++) {
            int m = a_m + p * 64;
            As[a_kq * 4 + 0][m] = pa[p].x;
            As[a_kq * 4 + 1][m] = pa[p].y;
            As[a_kq * 4 + 2][m] = pa[p].z;
            As[a_kq * 4 + 3][m] = pa[p].w;
        }
#pragma unroll
        for (int p = 0; p < 4; p++)
            Bs[b_kr + p * 4][b_col] = pb[p];
    };

    loadA(0);
    loadB(0);
    storeAB();
    __syncthreads();

    const int NT = KD / BK;
    for (int kt = 0; kt < NT; kt++) {
        const bool more = (kt + 1 < NT);
        if (more) {
            loadA((kt + 1) * BK);
            loadB((kt + 1) * BK);
        }
#pragma unroll
        for (int k = 0; k < BK; k++) {
            float4 a0 = *(const float4*)&As[k][mo];
            float4 a1 = *(const float4*)&As[k][mo + 4];
            float4 b0 = *(const float4*)&Bs[k][no];
            float a[TM] = {a0.x, a0.y, a0.z, a0.w, a1.x, a1.y, a1.z, a1.w};
            float b[TN] = {b0.x, b0.y, b0.z, b0.w};
#pragma unroll
            for (int i = 0; i < TM; i++)
#pragma unroll
                for (int j = 0; j < TN; j++)
                    acc[i][j] = fmaf(a[i], b[j], acc[i][j]);
        }
        __syncthreads();
        if (more) {
            storeAB();
            __syncthreads();
        }
    }

#pragma unroll
    for (int i = 0; i < TM; i++) {
        int row = bm + mo + i;
        float bv = bias[row];
        float4 o;
        o.x = acc[i][0] + bv;
        o.y = acc[i][1] + bv;
        o.z = acc[i][2] + bv;
        o.w = acc[i][3] + bv;
        *(float4*)(out + (size_t)row * NSP + bn + no) = o;
    }
}

// ---------------------------------------------------------------------------
extern "C" void kernel_launch(void* const* d_in, const int* in_sizes, int n_in,
                              void* d_out, int out_size)
{
    const float* x    = (const float*)d_in[0];
    const float* l1w  = (const float*)d_in[1];
    const float* l1b  = (const float*)d_in[2];
    const float* l2w  = (const float*)d_in[3];
    const float* l2b  = (const float*)d_in[4];
    const float* l3w  = (const float*)d_in[5];
    const float* l3b  = (const float*)d_in[6];
    const float* dfw  = (const float*)d_in[7];
    const float* dfb  = (const float*)d_in[8];
    const float* c3w  = (const float*)d_in[9];
    const float* c3b  = (const float*)d_in[10];

    float *h1, *h2, *offp;
    cudaGetSymbolAddress((void**)&h1,   g_h1);
    cudaGetSymbolAddress((void**)&h2,   g_h2);
    cudaGetSymbolAddress((void**)&offp, g_off);

    dim3 blk(NTHR);
    dim3 gMain(NSP / BN, (256 + BM - 1) / BM);  // 72 x 2
    dim3 gOff(NSP / BN, 1);                     // 72 x 1 (M=81)

    conv_gemm<true ><<<gMain, blk>>>(h1,   x,  l1w, l1b, 256);
    conv_gemm<true ><<<gMain, blk>>>(h2,   h1, l2w, l2b, 256);
    conv_gemm<true ><<<gMain, blk>>>(h1,   h2, l3w, l3b, 256);
    conv_gemm<false><<<gOff,  blk>>>(offp, h1, dfw, dfb, 81);
    deform_gemm<<<gMain, blk>>>((float*)d_out, x, offp, c3w, c3b);
}

// round 5
// speedup vs baseline: 1.0423x; 1.0397x over previous
#include <cuda_runtime.h>
#include <cstdint>

// Fixed problem shapes
#define T_   8
#define H_   24
#define W_   24
#define HW_  576          // H*W
#define NSP  4608         // T*H*W
#define CIN  256
#define NK   27
#define KD   (CIN * NK)   // 6912

// GEMM tiling
#define BM 128
#define BK 16
#define TM 8
#define NTHR 256
#define NT (KD / BK)      // 432

// Scratch (static device globals: allocation-free)
__device__ float g_h1[CIN * NSP];
__device__ float g_h2[CIN * NSP];
__device__ float g_off[81 * NSP];

// ---------------------------------------------------------------------------
// conv3d (3x3x3, pad 1) as implicit GEMM, double-buffered smem + reg frags.
//   C[M, NSP] = W[M, KD] * B[KD, NSP],  B(k,n) = in[cin, pos+tap] (0-padded)
// ---------------------------------------------------------------------------
template <int BN_, bool RELU>
__global__ __launch_bounds__(NTHR, 1)
void conv_gemm(float* __restrict__ out, const float* __restrict__ in,
               const float* __restrict__ wgt, const float* __restrict__ bias,
               int M)
{
    constexpr int TN_   = BN_ / 16;       // 64->4, 32->2
    constexpr int BSTEP = NTHR / BN_;     // 64->4, 32->8
    constexpr int RP    = BK / BSTEP;     // 64->4, 32->2

    __shared__ __align__(16) float As[2][BK][BM + 4];
    __shared__ __align__(16) float Bs[2][BK][BN_];
    __shared__ int Boff[NK * BN_];

    const int tid = threadIdx.x;
    const int bm = blockIdx.y * BM;
    const int bn = blockIdx.x * BN_;

    // compute mapping: 16 (n) x 16 (m) threads, each TM x TN_
    const int tx = tid & 15;
    const int ty = tid >> 4;
    const int mo = ty * TM;
    const int no = tx * TN_;

    // A load mapping: float4 along K
    const int a_kq = tid & 3;    // k quad
    const int a_m  = tid >> 2;   // 0..63, two passes (+64)
    // B load mapping
    const int b_col = tid % BN_;
    const int b_kr  = tid / BN_;

    // Preamble: per-(tap, col) spatial offset (or -1 if out of bounds)
    for (int e = tid; e < NK * BN_; e += NTHR) {
        int tap = e / BN_;
        int col = e % BN_;
        int nn = bn + col;
        int t  = nn / HW_;
        int hr = nn - t * HW_;
        int h  = hr / W_;
        int w  = hr - h * W_;
        int dt = tap / 9, r9 = tap - dt * 9;
        int dh = r9 / 3,  dw = r9 - dh * 3;
        int zt = t + dt - 1, zh = h + dh - 1, zw = w + dw - 1;
        bool v = ((unsigned)zt < T_) && ((unsigned)zh < H_) && ((unsigned)zw < W_);
        Boff[e] = v ? ((zt * H_ + zh) * W_ + zw) : -1;
    }

    float acc[TM][TN_];
#pragma unroll
    for (int i = 0; i < TM; i++)
#pragma unroll
        for (int j = 0; j < TN_; j++) acc[i][j] = 0.f;

    float4 pa[2];
    float  pb[RP];

    auto loadA = [&](int k0) {
#pragma unroll
        for (int p = 0; p < 2; p++) {
            int row = bm + a_m + p * 64;
            if (row < M) {
                const float* src = wgt + (size_t)row * KD + k0 + a_kq * 4;
                pa[p] = *(const float4*)src;
            } else {
                pa[p] = make_float4(0.f, 0.f, 0.f, 0.f);
            }
        }
    };

    auto loadB = [&](int k0) {
#pragma unroll
        for (int p = 0; p < RP; p++) {
            int kk  = k0 + b_kr + p * BSTEP;
            int cin = kk / NK;
            int tap = kk - cin * NK;
            int o   = Boff[tap * BN_ + b_col];
            pb[p] = (o >= 0) ? in[cin * NSP + o] : 0.f;
        }
    };

    auto storeAB = [&](int buf) {
#pragma unroll
        for (int p = 0; p < 2; p++) {
            int m = a_m + p * 64;
            As[buf][a_kq * 4 + 0][m] = pa[p].x;
            As[buf][a_kq * 4 + 1][m] = pa[p].y;
            As[buf][a_kq * 4 + 2][m] = pa[p].z;
            As[buf][a_kq * 4 + 3][m] = pa[p].w;
        }
#pragma unroll
        for (int p = 0; p < RP; p++)
            Bs[buf][b_kr + p * BSTEP][b_col] = pb[p];
    };

    __syncthreads();          // Boff ready
    loadA(0);
    loadB(0);
    storeAB(0);
    __syncthreads();

#pragma unroll 1
    for (int kt = 0; kt < NT; kt++) {
        const int  cur  = kt & 1;
        const bool more = (kt + 1) < NT;
        if (more) {
            loadA((kt + 1) * BK);
            loadB((kt + 1) * BK);
        }

        // k-level register fragment double buffering
        float a_f[2][TM];
        float b_f[2][TN_];
        *(float4*)&a_f[0][0] = *(const float4*)&As[cur][0][mo];
        *(float4*)&a_f[0][4] = *(const float4*)&As[cur][0][mo + 4];
        if constexpr (TN_ == 4)
            *(float4*)&b_f[0][0] = *(const float4*)&Bs[cur][0][no];
        else
            *(float2*)&b_f[0][0] = *(const float2*)&Bs[cur][0][no];

#pragma unroll
        for (int k = 0; k < BK; k++) {
            const int c = k & 1;
            if (k + 1 < BK) {
                const int nx = c ^ 1;
                *(float4*)&a_f[nx][0] = *(const float4*)&As[cur][k + 1][mo];
                *(float4*)&a_f[nx][4] = *(const float4*)&As[cur][k + 1][mo + 4];
                if constexpr (TN_ == 4)
                    *(float4*)&b_f[nx][0] = *(const float4*)&Bs[cur][k + 1][no];
                else
                    *(float2*)&b_f[nx][0] = *(const float2*)&Bs[cur][k + 1][no];
            }
#pragma unroll
            for (int i = 0; i < TM; i++)
#pragma unroll
                for (int j = 0; j < TN_; j++)
                    acc[i][j] = fmaf(a_f[c][i], b_f[c][j], acc[i][j]);
        }

        if (more) storeAB(cur ^ 1);
        __syncthreads();
    }

    // epilogue: bias (+ relu)
#pragma unroll
    for (int i = 0; i < TM; i++) {
        int row = bm + mo + i;
        if (row < M) {
            float bv = bias[row];
            if constexpr (TN_ == 4) {
                float4 o;
                o.x = acc[i][0] + bv;
                o.y = acc[i][1] + bv;
                o.z = acc[i][2] + bv;
                o.w = acc[i][3] + bv;
                if (RELU) {
                    o.x = fmaxf(o.x, 0.f);
                    o.y = fmaxf(o.y, 0.f);
                    o.z = fmaxf(o.z, 0.f);
                    o.w = fmaxf(o.w, 0.f);
                }
                *(float4*)(out + (size_t)row * NSP + bn + no) = o;
            } else {
                float2 o;
                o.x = acc[i][0] + bv;
                o.y = acc[i][1] + bv;
                if (RELU) {
                    o.x = fmaxf(o.x, 0.f);
                    o.y = fmaxf(o.y, 0.f);
                }
                *(float2*)(out + (size_t)row * NSP + bn + no) = o;
            }
        }
    }
}

// ---------------------------------------------------------------------------
// Deformable conv as implicit GEMM with trilinear-gathered B tile.
// Double-buffered smem + register fragments; positions cached per block.
// ---------------------------------------------------------------------------
#define DBN 64
__global__ __launch_bounds__(NTHR, 1)
void deform_gemm(float* __restrict__ out, const float* __restrict__ x,
                 const float* __restrict__ off, const float* __restrict__ wgt,
                 const float* __restrict__ bias)
{
    __shared__ __align__(16) float As[2][BK][BM + 4];
    __shared__ __align__(16) float Bs[2][BK][DBN];
    __shared__ float ppt[NK * DBN];
    __shared__ float pph[NK * DBN];
    __shared__ float ppw[NK * DBN];

    const int tid = threadIdx.x;
    const int bm = blockIdx.y * BM;
    const int bn = blockIdx.x * DBN;

    const int tx = tid & 15;
    const int ty = tid >> 4;
    const int mo = ty * TM;
    const int no = tx * 4;

    const int a_kq = tid & 3;
    const int a_m  = tid >> 2;
    const int b_col = tid & 63;
    const int b_kr  = tid >> 6;

    // Precompute sample positions for all (tap, col) of this block
    for (int e = tid; e < NK * DBN; e += NTHR) {
        int tap = e >> 6;
        int col = e & 63;
        int nn = bn + col;
        int tt = nn / HW_;
        int rr = nn - tt * HW_;
        int hh = rr / W_;
        int ww = rr - hh * W_;
        int dt = tap / 9;
        int r9 = tap - dt * 9;
        int dh = r9 / 3;
        int dw = r9 - dh * 3;
        float ot = off[(tap * 3 + 0) * NSP + nn];
        float oh = off[(tap * 3 + 1) * NSP + nn];
        float ow = off[(tap * 3 + 2) * NSP + nn];
        ppt[e] = (float)(tt + dt - 1) + ot;
        pph[e] = (float)(hh + dh - 1) + oh;
        ppw[e] = (float)(ww + dw - 1) + ow;
    }

    float acc[TM][4];
#pragma unroll
    for (int i = 0; i < TM; i++)
#pragma unroll
        for (int j = 0; j < 4; j++) acc[i][j] = 0.f;

    float4 pa[2];
    float  pb[4];

    auto loadA = [&](int k0) {
#pragma unroll
        for (int p = 0; p < 2; p++) {
            int row = bm + a_m + p * 64;
            const float* src = wgt + (size_t)row * KD + k0 + a_kq * 4;
            pa[p] = *(const float4*)src;
        }
    };

    auto loadB = [&](int k0) {
#pragma unroll
        for (int p = 0; p < 4; p++) {
            int kk  = k0 + b_kr + p * 4;
            int cin = kk / NK;
            int tap = kk - cin * NK;
            int e   = tap * DBN + b_col;
            float pt = ppt[e], ph = pph[e], pw = ppw[e];
            float ft = floorf(pt), fh = floorf(ph), fw = floorf(pw);
            float at = pt - ft, ah = ph - fh, aw = pw - fw;
            int it = (int)ft, ih = (int)fh, iw = (int)fw;
            int t1 = it + 1, h1 = ih + 1, w1 = iw + 1;
            float wt0 = ((unsigned)it < T_) ? (1.f - at) : 0.f;
            float wt1 = ((unsigned)t1 < T_) ? at : 0.f;
            float wh0 = ((unsigned)ih < H_) ? (1.f - ah) : 0.f;
            float wh1 = ((unsigned)h1 < H_) ? ah : 0.f;
            float ww0 = ((unsigned)iw < W_) ? (1.f - aw) : 0.f;
            float ww1 = ((unsigned)w1 < W_) ? aw : 0.f;
            int tc0 = min(max(it, 0), T_ - 1), tc1 = min(max(t1, 0), T_ - 1);
            int hc0 = min(max(ih, 0), H_ - 1), hc1 = min(max(h1, 0), H_ - 1);
            int wc0 = min(max(iw, 0), W_ - 1), wc1 = min(max(w1, 0), W_ - 1);
            const float* xc = x + cin * NSP;
            int r00 = (tc0 * H_ + hc0) * W_;
            int r01 = (tc0 * H_ + hc1) * W_;
            int r10 = (tc1 * H_ + hc0) * W_;
            int r11 = (tc1 * H_ + hc1) * W_;
            float w00 = wt0 * wh0, w01 = wt0 * wh1;
            float w10 = wt1 * wh0, w11 = wt1 * wh1;
            float v;
            v  = (w00 * ww0) * xc[r00 + wc0];
            v += (w00 * ww1) * xc[r00 + wc1];
            v += (w01 * ww0) * xc[r01 + wc0];
            v += (w01 * ww1) * xc[r01 + wc1];
            v += (w10 * ww0) * xc[r10 + wc0];
            v += (w10 * ww1) * xc[r10 + wc1];
            v += (w11 * ww0) * xc[r11 + wc0];
            v += (w11 * ww1) * xc[r11 + wc1];
            pb[p] = v;
        }
    };

    auto storeAB = [&](int buf) {
#pragma unroll
        for (int p = 0; p < 2; p++) {
            int m = a_m + p * 64;
            As[buf][a_kq * 4 + 0][m] = pa[p].x;
            As[buf][a_kq * 4 + 1][m] = pa[p].y;
            As[buf][a_kq * 4 + 2][m] = pa[p].z;
            As[buf][a_kq * 4 + 3][m] = pa[p].w;
        }
#pragma unroll
        for (int p = 0; p < 4; p++)
            Bs[buf][b_kr + p * 4][b_col] = pb[p];
    };

    __syncthreads();          // positions ready
    loadA(0);
    loadB(0);
    storeAB(0);
    __syncthreads();

#pragma unroll 1
    for (int kt = 0; kt < NT; kt++) {
        const int  cur  = kt & 1;
        const bool more = (kt + 1) < NT;
        if (more) {
            loadA((kt + 1) * BK);
            loadB((kt + 1) * BK);
        }

        float a_f[2][TM];
        float b_f[2][4];
        *(float4*)&a_f[0][0] = *(const float4*)&As[cur][0][mo];
        *(float4*)&a_f[0][4] = *(const float4*)&As[cur][0][mo + 4];
        *(float4*)&b_f[0][0] = *(const float4*)&Bs[cur][0][no];

#pragma unroll
        for (int k = 0; k < BK; k++) {
            const int c = k & 1;
            if (k + 1 < BK) {
                const int nx = c ^ 1;
                *(float4*)&a_f[nx][0] = *(const float4*)&As[cur][k + 1][mo];
                *(float4*)&a_f[nx][4] = *(const float4*)&As[cur][k + 1][mo + 4];
                *(float4*)&b_f[nx][0] = *(const float4*)&Bs[cur][k + 1][no];
            }
#pragma unroll
            for (int i = 0; i < TM; i++)
#pragma unroll
                for (int j = 0; j < 4; j++)
                    acc[i][j] = fmaf(a_f[c][i], b_f[c][j], acc[i][j]);
        }

        if (more) storeAB(cur ^ 1);
        __syncthreads();
    }

#pragma unroll
    for (int i = 0; i < TM; i++) {
        int row = bm + mo + i;
        float bv = bias[row];
        float4 o;
        o.x = acc[i][0] + bv;
        o.y = acc[i][1] + bv;
        o.z = acc[i][2] + bv;
        o.w = acc[i][3] + bv;
        *(float4*)(out + (size_t)row * NSP + bn + no) = o;
    }
}

// ---------------------------------------------------------------------------
extern "C" void kernel_launch(void* const* d_in, const int* in_sizes, int n_in,
                              void* d_out, int out_size)
{
    const float* x    = (const float*)d_in[0];
    const float* l1w  = (const float*)d_in[1];
    const float* l1b  = (const float*)d_in[2];
    const float* l2w  = (const float*)d_in[3];
    const float* l2b  = (const float*)d_in[4];
    const float* l3w  = (const float*)d_in[5];
    const float* l3b  = (const float*)d_in[6];
    const float* dfw  = (const float*)d_in[7];
    const float* dfb  = (const float*)d_in[8];
    const float* c3w  = (const float*)d_in[9];
    const float* c3b  = (const float*)d_in[10];

    float *h1, *h2, *offp;
    cudaGetSymbolAddress((void**)&h1,   g_h1);
    cudaGetSymbolAddress((void**)&h2,   g_h2);
    cudaGetSymbolAddress((void**)&offp, g_off);

    dim3 blk(NTHR);
    dim3 gMain(NSP / 64, 2);   // 72 x 2 = 144 blocks (BN=64, M=256)
    dim3 gOff(NSP / 32, 1);    // 144 x 1 blocks (BN=32, M=81)

    conv_gemm<64, true ><<<gMain, blk>>>(h1,   x,  l1w, l1b, 256);
    conv_gemm<64, true ><<<gMain, blk>>>(h2,   h1, l2w, l2b, 256);
    conv_gemm<64, true ><<<gMain, blk>>>(h1,   h2, l3w, l3b, 256);
    conv_gemm<32, false><<<gOff,  blk>>>(offp, h1, dfw, dfb, 81);
    deform_gemm<<<gMain, blk>>>((float*)d_out, x, offp, c3w, c3b);
}